// round 1
// baseline (speedup 1.0000x reference)
#include <cuda_runtime.h>
#include <math.h>

#define NU 100000
#define NI 50000
#define DD 64
#define ES 800000
#define EUI 1000000
#define EIU 1000000
#define ALPHA_LRELU 0.2f
#define CDIV(a,b) (((a)+(b)-1)/(b))

// ---------------- scratch (device globals; no runtime allocation) -------------
__device__ float g_v[2*(ES+EUI+EIU)];          // per-edge softmax scratch (v, then e)
__device__ float g_mx[4*NU + 2*NI];            // row maxes: sn1,sn2,ci1,ci2 (U each), ic1,ic2 (I each)
__device__ float g_sm[4*NU + 2*NI];            // row sums, same layout
__device__ float g_node[(4*NU + 3*NI) * DD];   // ufi, ufu (U*D), ifu (I*D), u1, u2 (U*D), i1, i2 (I*D)

// ---------------- kernels ----------------------------------------------------
__global__ void k_zero4(float4* __restrict__ p, int n4) {
    int i = blockIdx.x * blockDim.x + threadIdx.x;
    if (i < n4) p[i] = make_float4(0.f, 0.f, 0.f, 0.f);
}

// pass1: v = exp(sigmoid(raw*w+b)); row max via atomicMax on positive-float bits
__global__ void k_att_pass1(const float* __restrict__ raw1, const float* __restrict__ raw2,
                            const int* __restrict__ row,
                            const float* __restrict__ law, const float* __restrict__ lab,
                            int j1, int j2,
                            float* __restrict__ v1, float* __restrict__ v2,
                            float* __restrict__ mx1, float* __restrict__ mx2, int E) {
    int e = blockIdx.x * blockDim.x + threadIdx.x;
    if (e >= E) return;
    int r = row[e];
    float x1 = raw1[e] * law[j1] + lab[j1];
    float x2 = raw2[e] * law[j2] + lab[j2];
    float a = expf(1.f / (1.f + expf(-x1)));
    float b = expf(1.f / (1.f + expf(-x2)));
    v1[e] = a; v2[e] = b;
    atomicMax((int*)(mx1 + r), __float_as_int(a));   // all values > 1 > 0 -> bit max valid
    atomicMax((int*)(mx2 + r), __float_as_int(b));
}

// pass2: e = exp(v - max); row sum
__global__ void k_att_pass2(const int* __restrict__ row,
                            float* __restrict__ v1, float* __restrict__ v2,
                            const float* __restrict__ mx1, const float* __restrict__ mx2,
                            float* __restrict__ sm1, float* __restrict__ sm2, int E) {
    int e = blockIdx.x * blockDim.x + threadIdx.x;
    if (e >= E) return;
    int r = row[e];
    float e1 = expf(v1[e] - mx1[r]);
    float e2 = expf(v2[e] - mx2[r]);
    v1[e] = e1; v2[e] = e2;
    atomicAdd(sm1 + r, e1);
    atomicAdd(sm2 + r, e2);
}

// SpMM: out[row[e]] += (ev[e]/(sum[row[e]]+eps)) * x[col[e]]   (warp per edge)
__global__ void __launch_bounds__(256) k_spmm(const float* __restrict__ ev,
                                              const float* __restrict__ sm,
                                              const int* __restrict__ row,
                                              const int* __restrict__ col,
                                              const float* __restrict__ x,
                                              float* __restrict__ out, int E) {
    int e = (blockIdx.x * blockDim.x + threadIdx.x) >> 5;
    int lane = threadIdx.x & 31;
    if (e >= E) return;
    int r = row[e], c = col[e];
    float att = ev[e] / (sm[r] + 1e-12f);
    const float* xs = x + (size_t)c * DD;
    float* o = out + (size_t)r * DD;
    atomicAdd(o + lane,      att * xs[lane]);
    atomicAdd(o + lane + 32, att * xs[lane + 32]);
}

__device__ __forceinline__ float att_scalar(float dot, float b1, float w2, float b2) {
    float h = tanhf(dot + b1);
    float g = h * w2 + b2;
    g = g > 0.f ? g : ALPHA_LRELU * g;
    return expf(g);
}

// user combine: warp per node
__global__ void __launch_bounds__(256) k_user(const float* __restrict__ u,
                                              const float* __restrict__ ufi,
                                              const float* __restrict__ ufu,
                                              const float* __restrict__ a1W,
                                              const float* __restrict__ a1b,
                                              const float* __restrict__ a2w,
                                              const float* __restrict__ a2b,
                                              int k, float* __restrict__ out) {
    int node = (blockIdx.x * blockDim.x + threadIdx.x) >> 5;
    int lane = threadIdx.x & 31;
    if (node >= NU) return;
    const float* Wa = a1W + (size_t)k * 128;
    const float* Wb = a1W + (size_t)(k + 1) * 128;
    const float* up  = u   + (size_t)node * DD;
    const float* fip = ufi + (size_t)node * DD;
    const float* fup = ufu + (size_t)node * DD;
    float u0 = up[lane],  u1v = up[lane + 32];
    float fi0 = fip[lane], fi1 = fip[lane + 32];
    float fu0 = fup[lane], fu1 = fup[lane + 32];
    float dint = u0 * Wa[lane] + u1v * Wa[lane + 32] + fi0 * Wa[64 + lane] + fi1 * Wa[96 + lane];
    float dsoc = u0 * Wb[lane] + u1v * Wb[lane + 32] + fu0 * Wb[64 + lane] + fu1 * Wb[96 + lane];
    #pragma unroll
    for (int o = 16; o; o >>= 1) {
        dint += __shfl_xor_sync(0xffffffffu, dint, o);
        dsoc += __shfl_xor_sync(0xffffffffu, dsoc, o);
    }
    float aint = att_scalar(dint, a1b[k],     a2w[k],     a2b[k])     + 0.7f;
    float asoc = att_scalar(dsoc, a1b[k + 1], a2w[k + 1], a2b[k + 1]) + 0.3f;
    float s = aint + asoc;
    float wi = 0.5f * aint / s, ws = 0.5f * asoc / s;
    float* op = out + (size_t)node * DD;
    op[lane]      = 0.5f * u0  + wi * fi0 + ws * fu0;
    op[lane + 32] = 0.5f * u1v + wi * fi1 + ws * fu1;
}

// item combine: warp per node
__global__ void __launch_bounds__(256) k_item(const float* __restrict__ it,
                                              const float* __restrict__ ifu,
                                              const float* __restrict__ a1W,
                                              const float* __restrict__ a1b,
                                              const float* __restrict__ a2w,
                                              const float* __restrict__ a2b,
                                              int k, float* __restrict__ out) {
    int node = (blockIdx.x * blockDim.x + threadIdx.x) >> 5;
    int lane = threadIdx.x & 31;
    if (node >= NI) return;
    const float* Wa = a1W + (size_t)k * 128;
    const float* Wb = a1W + (size_t)(k + 1) * 128;
    const float* ip = it  + (size_t)node * DD;
    const float* fp = ifu + (size_t)node * DD;
    float i0 = ip[lane], i1v = ip[lane + 32];
    float f0 = fp[lane], f1  = fp[lane + 32];
    float dself = i0 * (Wa[lane] + Wa[64 + lane]) + i1v * (Wa[lane + 32] + Wa[96 + lane]);
    float dcust = i0 * Wb[lane] + i1v * Wb[lane + 32] + f0 * Wb[64 + lane] + f1 * Wb[96 + lane];
    #pragma unroll
    for (int o = 16; o; o >>= 1) {
        dself += __shfl_xor_sync(0xffffffffu, dself, o);
        dcust += __shfl_xor_sync(0xffffffffu, dcust, o);
    }
    float aself = att_scalar(dself, a1b[k],     a2w[k],     a2b[k])     + 1.0f;
    float acust = att_scalar(dcust, a1b[k + 1], a2w[k + 1], a2b[k + 1]) + 1.0f;
    float s = aself + acust;
    float wsf = aself / s, wcu = acust / s;
    float* op = out + (size_t)node * DD;
    op[lane]      = wsf * i0  + wcu * f0;
    op[lane + 32] = wsf * i1v + wcu * f1;
}

// final scorer: warp per (user, item) pair
__global__ void __launch_bounds__(256) k_final(const float* __restrict__ u0,
                                               const float* __restrict__ u1,
                                               const float* __restrict__ u2,
                                               const float* __restrict__ i0,
                                               const float* __restrict__ i1,
                                               const float* __restrict__ i2,
                                               const int* __restrict__ uidx,
                                               const int* __restrict__ iidx,
                                               float* __restrict__ out, int B) {
    int b = (blockIdx.x * blockDim.x + threadIdx.x) >> 5;
    int lane = threadIdx.x & 31;
    if (b >= B) return;
    size_t uo = (size_t)uidx[b] * DD, io = (size_t)iidx[b] * DD;
    float d = u0[uo + lane] * i0[io + lane] + u0[uo + lane + 32] * i0[io + lane + 32]
            + u1[uo + lane] * i1[io + lane] + u1[uo + lane + 32] * i1[io + lane + 32]
            + u2[uo + lane] * i2[io + lane] + u2[uo + lane + 32] * i2[io + lane + 32];
    #pragma unroll
    for (int o = 16; o; o >>= 1) d += __shfl_xor_sync(0xffffffffu, d, o);
    if (lane == 0) out[b] = 1.f / (1.f + expf(-d));
}

// ---------------- launch ------------------------------------------------------
extern "C" void kernel_launch(void* const* d_in, const int* in_sizes, int n_in,
                              void* d_out, int out_size) {
    const float* u_emb = (const float*)d_in[0];
    const float* i_emb = (const float*)d_in[1];
    const float* snii1 = (const float*)d_in[2];
    const float* snii2 = (const float*)d_in[3];
    const float* ciii1 = (const float*)d_in[4];
    const float* ciii2 = (const float*)d_in[5];
    const float* icii1 = (const float*)d_in[6];
    const float* icii2 = (const float*)d_in[7];
    const float* law   = (const float*)d_in[8];
    const float* lab   = (const float*)d_in[9];
    const float* a1W   = (const float*)d_in[10];
    const float* a1b   = (const float*)d_in[11];
    const float* a2w   = (const float*)d_in[12];
    const float* a2b   = (const float*)d_in[13];
    const int* sn_row  = (const int*)d_in[14];
    const int* sn_col  = (const int*)d_in[15];
    const int* ci_row  = (const int*)d_in[16];
    const int* ci_col  = (const int*)d_in[17];
    const int* ic_row  = (const int*)d_in[18];
    const int* ic_col  = (const int*)d_in[19];
    const int* uidx    = (const int*)d_in[20];
    const int* iidx    = (const int*)d_in[21];
    float* out = (float*)d_out;
    int B = out_size;

    float *vp, *mxp, *smp, *np;
    cudaGetSymbolAddress((void**)&vp, g_v);
    cudaGetSymbolAddress((void**)&mxp, g_mx);
    cudaGetSymbolAddress((void**)&smp, g_sm);
    cudaGetSymbolAddress((void**)&np, g_node);

    float* v_sn1 = vp;              float* v_sn2 = v_sn1 + ES;
    float* v_ci1 = v_sn2 + ES;      float* v_ci2 = v_ci1 + EUI;
    float* v_ic1 = v_ci2 + EUI;     float* v_ic2 = v_ic1 + EIU;

    float* mx_sn1 = mxp;            float* mx_sn2 = mx_sn1 + NU;
    float* mx_ci1 = mx_sn2 + NU;    float* mx_ci2 = mx_ci1 + NU;
    float* mx_ic1 = mx_ci2 + NU;    float* mx_ic2 = mx_ic1 + NI;
    float* sm_sn1 = smp;            float* sm_sn2 = sm_sn1 + NU;
    float* sm_ci1 = sm_sn2 + NU;    float* sm_ci2 = sm_ci1 + NU;
    float* sm_ic1 = sm_ci2 + NU;    float* sm_ic2 = sm_ic1 + NI;

    float* ufi = np;
    float* ufu = ufi + (size_t)NU * DD;
    float* ifu = ufu + (size_t)NU * DD;
    float* u1  = ifu + (size_t)NI * DD;
    float* u2  = u1  + (size_t)NU * DD;
    float* i1  = u2  + (size_t)NU * DD;
    float* i2  = i1  + (size_t)NI * DD;

    const int T = 256;
    int nstat4 = (4 * NU + 2 * NI) / 4;
    k_zero4<<<CDIV(nstat4, T), T>>>((float4*)mxp, nstat4);
    k_zero4<<<CDIV(nstat4, T), T>>>((float4*)smp, nstat4);

    // softmax pass 1 (paired)
    k_att_pass1<<<CDIV(ES, T), T>>>(snii1, snii2, sn_row, law, lab, 0, 1, v_sn1, v_sn2, mx_sn1, mx_sn2, ES);
    k_att_pass1<<<CDIV(EUI, T), T>>>(ciii1, ciii2, ci_row, law, lab, 2, 3, v_ci1, v_ci2, mx_ci1, mx_ci2, EUI);
    k_att_pass1<<<CDIV(EIU, T), T>>>(icii1, icii2, ic_row, law, lab, 4, 5, v_ic1, v_ic2, mx_ic1, mx_ic2, EIU);
    // softmax pass 2 (paired)
    k_att_pass2<<<CDIV(ES, T), T>>>(sn_row, v_sn1, v_sn2, mx_sn1, mx_sn2, sm_sn1, sm_sn2, ES);
    k_att_pass2<<<CDIV(EUI, T), T>>>(ci_row, v_ci1, v_ci2, mx_ci1, mx_ci2, sm_ci1, sm_ci2, EUI);
    k_att_pass2<<<CDIV(EIU, T), T>>>(ic_row, v_ic1, v_ic2, mx_ic1, mx_ic2, sm_ic1, sm_ic2, EIU);

    int nz4 = (2 * NU + NI) * DD / 4;

    // ---- layer 1 ----
    k_zero4<<<CDIV(nz4, T), T>>>((float4*)ufi, nz4);
    k_spmm<<<CDIV(EUI * 32, T), T>>>(v_ci1, sm_ci1, ci_row, ci_col, i_emb, ufi, EUI);
    k_spmm<<<CDIV(ES  * 32, T), T>>>(v_sn1, sm_sn1, sn_row, sn_col, u_emb, ufu, ES);
    k_spmm<<<CDIV(EIU * 32, T), T>>>(v_ic1, sm_ic1, ic_row, ic_col, u_emb, ifu, EIU);
    k_user<<<CDIV(NU * 32, T), T>>>(u_emb, ufi, ufu, a1W, a1b, a2w, a2b, 0, u1);
    k_item<<<CDIV(NI * 32, T), T>>>(i_emb, ifu, a1W, a1b, a2w, a2b, 4, i1);

    // ---- layer 2 ----
    k_zero4<<<CDIV(nz4, T), T>>>((float4*)ufi, nz4);
    k_spmm<<<CDIV(EUI * 32, T), T>>>(v_ci2, sm_ci2, ci_row, ci_col, i1, ufi, EUI);
    k_spmm<<<CDIV(ES  * 32, T), T>>>(v_sn2, sm_sn2, sn_row, sn_col, u1, ufu, ES);
    k_spmm<<<CDIV(EIU * 32, T), T>>>(v_ic2, sm_ic2, ic_row, ic_col, u1, ifu, EIU);
    k_user<<<CDIV(NU * 32, T), T>>>(u1, ufi, ufu, a1W, a1b, a2w, a2b, 2, u2);
    k_item<<<CDIV(NI * 32, T), T>>>(i1, ifu, a1W, a1b, a2w, a2b, 6, i2);

    // ---- final ----
    k_final<<<CDIV(B * 32, T), T>>>(u_emb, u1, u2, i_emb, i1, i2, uidx, iidx, out, B);
}

// round 2
// speedup vs baseline: 2.1784x; 2.1784x over previous
#include <cuda_runtime.h>
#include <math.h>

#define NU 100000
#define NI 50000
#define DD 64
#define ES 800000
#define EUI 1000000
#define EIU 1000000
#define ETOT (ES + EUI + EIU)
#define NROWS (2 * NU + NI)
#define NSCANBLK ((NROWS + 2047) / 2048)
#define ALPHA_LRELU 0.2f
#define CDIV(a,b) (((a)+(b)-1)/(b))

// ---------------- scratch (device globals; no runtime allocation) -------------
__device__ float2 g_v12a[ETOT];     // edge logits, original order (v1, v2)
__device__ float2 g_v12b[ETOT];     // edge att, row-sorted order
__device__ int    g_colp[ETOT];     // col, row-sorted order
__device__ int    g_cnt[NROWS];     // histogram
__device__ int    g_rowptr[NROWS + 1];
__device__ int    g_cursor[NROWS];
__device__ int    g_bsum[NSCANBLK + 1];
__device__ float  g_node[(4*NU + 3*NI) * DD];  // ufi, ufu (U*D), ifu (I*D), u1, u2, i1, i2

// ---------------- helpers ------------------------------------------------------
__device__ __forceinline__ float warp_sum(float v) {
    #pragma unroll
    for (int o = 16; o; o >>= 1) v += __shfl_xor_sync(0xffffffffu, v, o);
    return v;
}
__device__ __forceinline__ float warp_max(float v) {
    #pragma unroll
    for (int o = 16; o; o >>= 1) v = fmaxf(v, __shfl_xor_sync(0xffffffffu, v, o));
    return v;
}

// ---------------- CSR build ----------------------------------------------------
__global__ void k_zero_int(int* __restrict__ p, int n) {
    int i = blockIdx.x * blockDim.x + threadIdx.x;
    if (i < n) p[i] = 0;
}

__global__ void k_hist(const int* __restrict__ row, int rowbase, int E, int* __restrict__ cnt) {
    int e = blockIdx.x * blockDim.x + threadIdx.x;
    if (e < E) atomicAdd(cnt + rowbase + row[e], 1);
}

// per-block exclusive scan (2048 elems / block of 1024 threads)
__global__ void __launch_bounds__(1024) k_scan1(const int* __restrict__ cnt,
                                                int* __restrict__ out,
                                                int* __restrict__ bsum, int n) {
    __shared__ int sh[1024];
    int t = threadIdx.x;
    int i0 = blockIdx.x * 2048 + 2 * t;
    int c0 = (i0 < n) ? cnt[i0] : 0;
    int c1 = (i0 + 1 < n) ? cnt[i0 + 1] : 0;
    int p = c0 + c1;
    sh[t] = p;
    __syncthreads();
    #pragma unroll
    for (int off = 1; off < 1024; off <<= 1) {
        int add = (t >= off) ? sh[t - off] : 0;
        __syncthreads();
        sh[t] += add;
        __syncthreads();
    }
    int excl = sh[t] - p;
    if (i0 < n) out[i0] = excl;
    if (i0 + 1 < n) out[i0 + 1] = excl + c0;
    if (t == 1023) bsum[blockIdx.x] = sh[t];
}

// scan of block sums (single block)
__global__ void __launch_bounds__(256) k_scan2(int* __restrict__ bsum, int nb) {
    __shared__ int sh[256];
    int t = threadIdx.x;
    int v = (t < nb) ? bsum[t] : 0;
    sh[t] = v;
    __syncthreads();
    #pragma unroll
    for (int off = 1; off < 256; off <<= 1) {
        int add = (t >= off) ? sh[t - off] : 0;
        __syncthreads();
        sh[t] += add;
        __syncthreads();
    }
    if (t < nb) bsum[t] = sh[t] - v;   // exclusive
}

__global__ void k_scan3(int* __restrict__ rowptr, int* __restrict__ cursor,
                        const int* __restrict__ bsum, int n) {
    int i = blockIdx.x * blockDim.x + threadIdx.x;
    if (i < n) {
        int v = rowptr[i] + bsum[i >> 11];
        rowptr[i] = v;
        cursor[i] = v;
    }
    if (i == 0) rowptr[n] = ETOT;
}

// edge logits in original order: v = exp(sigmoid(raw*w+b))
__global__ void k_logit(const float* __restrict__ raw1, const float* __restrict__ raw2,
                        const float* __restrict__ law, const float* __restrict__ lab,
                        int j1, int j2, float2* __restrict__ v12, int E) {
    int e = blockIdx.x * blockDim.x + threadIdx.x;
    if (e >= E) return;
    float x1 = raw1[e] * law[j1] + lab[j1];
    float x2 = raw2[e] * law[j2] + lab[j2];
    v12[e] = make_float2(expf(1.f / (1.f + expf(-x1))),
                         expf(1.f / (1.f + expf(-x2))));
}

// scatter edges into row-sorted order
__global__ void k_scatter(const int* __restrict__ row, const int* __restrict__ col,
                          const float2* __restrict__ v12src, int rowbase, int E,
                          int* __restrict__ cursor, int* __restrict__ colp,
                          float2* __restrict__ v12dst) {
    int e = blockIdx.x * blockDim.x + threadIdx.x;
    if (e >= E) return;
    int pos = atomicAdd(cursor + rowbase + row[e], 1);
    colp[pos] = col[e];
    v12dst[pos] = v12src[e];
}

// row softmax over both components, in place, warp per row (atomic-free)
__global__ void __launch_bounds__(256) k_softmax(const int* __restrict__ rowptr,
                                                 float2* __restrict__ v12) {
    int r = (blockIdx.x * blockDim.x + threadIdx.x) >> 5;
    int lane = threadIdx.x & 31;
    if (r >= NROWS) return;
    int s = rowptr[r], e = rowptr[r + 1];
    int len = e - s;
    if (len == 0) return;
    if (len <= 128) {
        float2 vals[4];
        int cnt = 0;
        float m1 = -1e30f, m2 = -1e30f;
        for (int j = s + lane; j < e; j += 32) {
            float2 v = v12[j];
            vals[cnt++] = v;
            m1 = fmaxf(m1, v.x); m2 = fmaxf(m2, v.y);
        }
        m1 = warp_max(m1); m2 = warp_max(m2);
        float s1 = 0.f, s2 = 0.f;
        #pragma unroll
        for (int k = 0; k < 4; k++) if (k < cnt) {
            vals[k].x = expf(vals[k].x - m1);
            vals[k].y = expf(vals[k].y - m2);
            s1 += vals[k].x; s2 += vals[k].y;
        }
        s1 = warp_sum(s1); s2 = warp_sum(s2);
        float inv1 = 1.f / (s1 + 1e-12f), inv2 = 1.f / (s2 + 1e-12f);
        int k = 0;
        for (int j = s + lane; j < e; j += 32, k++)
            v12[j] = make_float2(vals[k].x * inv1, vals[k].y * inv2);
    } else {
        float m1 = -1e30f, m2 = -1e30f;
        for (int j = s + lane; j < e; j += 32) {
            float2 v = v12[j];
            m1 = fmaxf(m1, v.x); m2 = fmaxf(m2, v.y);
        }
        m1 = warp_max(m1); m2 = warp_max(m2);
        float s1 = 0.f, s2 = 0.f;
        for (int j = s + lane; j < e; j += 32) {
            float2 v = v12[j];
            s1 += expf(v.x - m1); s2 += expf(v.y - m2);
        }
        s1 = warp_sum(s1); s2 = warp_sum(s2);
        float inv1 = 1.f / (s1 + 1e-12f), inv2 = 1.f / (s2 + 1e-12f);
        for (int j = s + lane; j < e; j += 32) {
            float2 v = v12[j];
            v12[j] = make_float2(expf(v.x - m1) * inv1, expf(v.y - m2) * inv2);
        }
    }
}

// SpMM: warp per row, register accumulate, no atomics
template<int COMP>
__global__ void __launch_bounds__(256) k_spmm_row(const float2* __restrict__ v12,
                                                  const int* __restrict__ colp,
                                                  const int* __restrict__ rowptr,
                                                  const float2* __restrict__ x2,
                                                  float2* __restrict__ out2,
                                                  int rowbase, int nrows) {
    int r = (blockIdx.x * blockDim.x + threadIdx.x) >> 5;
    int lane = threadIdx.x & 31;
    if (r >= nrows) return;
    int s = rowptr[rowbase + r], e = rowptr[rowbase + r + 1];
    float2 acc = make_float2(0.f, 0.f);
    int j = s;
    for (; j + 2 <= e; j += 2) {
        int c0 = __ldg(colp + j), c1 = __ldg(colp + j + 1);
        float2 a0 = __ldg(v12 + j), a1 = __ldg(v12 + j + 1);
        float2 x0 = __ldg(x2 + (size_t)c0 * 32 + lane);
        float2 x1 = __ldg(x2 + (size_t)c1 * 32 + lane);
        float w0 = COMP ? a0.y : a0.x;
        float w1 = COMP ? a1.y : a1.x;
        acc.x += w0 * x0.x + w1 * x1.x;
        acc.y += w0 * x0.y + w1 * x1.y;
    }
    if (j < e) {
        int c0 = __ldg(colp + j);
        float2 a0 = __ldg(v12 + j);
        float2 x0 = __ldg(x2 + (size_t)c0 * 32 + lane);
        float w0 = COMP ? a0.y : a0.x;
        acc.x += w0 * x0.x;
        acc.y += w0 * x0.y;
    }
    out2[(size_t)r * 32 + lane] = acc;
}

// ---------------- combine + final ----------------------------------------------
__device__ __forceinline__ float att_scalar(float dot, float b1, float w2, float b2) {
    float h = tanhf(dot + b1);
    float g = h * w2 + b2;
    g = g > 0.f ? g : ALPHA_LRELU * g;
    return expf(g);
}

__global__ void __launch_bounds__(256) k_user(const float* __restrict__ u,
                                              const float* __restrict__ ufi,
                                              const float* __restrict__ ufu,
                                              const float* __restrict__ a1W,
                                              const float* __restrict__ a1b,
                                              const float* __restrict__ a2w,
                                              const float* __restrict__ a2b,
                                              int k, float* __restrict__ out) {
    int node = (blockIdx.x * blockDim.x + threadIdx.x) >> 5;
    int lane = threadIdx.x & 31;
    if (node >= NU) return;
    const float* Wa = a1W + (size_t)k * 128;
    const float* Wb = a1W + (size_t)(k + 1) * 128;
    const float* up  = u   + (size_t)node * DD;
    const float* fip = ufi + (size_t)node * DD;
    const float* fup = ufu + (size_t)node * DD;
    float u0 = up[lane],  u1v = up[lane + 32];
    float fi0 = fip[lane], fi1 = fip[lane + 32];
    float fu0 = fup[lane], fu1 = fup[lane + 32];
    float dint = u0 * Wa[lane] + u1v * Wa[lane + 32] + fi0 * Wa[64 + lane] + fi1 * Wa[96 + lane];
    float dsoc = u0 * Wb[lane] + u1v * Wb[lane + 32] + fu0 * Wb[64 + lane] + fu1 * Wb[96 + lane];
    dint = warp_sum(dint); dsoc = warp_sum(dsoc);
    float aint = att_scalar(dint, a1b[k],     a2w[k],     a2b[k])     + 0.7f;
    float asoc = att_scalar(dsoc, a1b[k + 1], a2w[k + 1], a2b[k + 1]) + 0.3f;
    float s = aint + asoc;
    float wi = 0.5f * aint / s, ws = 0.5f * asoc / s;
    float* op = out + (size_t)node * DD;
    op[lane]      = 0.5f * u0  + wi * fi0 + ws * fu0;
    op[lane + 32] = 0.5f * u1v + wi * fi1 + ws * fu1;
}

__global__ void __launch_bounds__(256) k_item(const float* __restrict__ it,
                                              const float* __restrict__ ifu,
                                              const float* __restrict__ a1W,
                                              const float* __restrict__ a1b,
                                              const float* __restrict__ a2w,
                                              const float* __restrict__ a2b,
                                              int k, float* __restrict__ out) {
    int node = (blockIdx.x * blockDim.x + threadIdx.x) >> 5;
    int lane = threadIdx.x & 31;
    if (node >= NI) return;
    const float* Wa = a1W + (size_t)k * 128;
    const float* Wb = a1W + (size_t)(k + 1) * 128;
    const float* ip = it  + (size_t)node * DD;
    const float* fp = ifu + (size_t)node * DD;
    float i0 = ip[lane], i1v = ip[lane + 32];
    float f0 = fp[lane], f1  = fp[lane + 32];
    float dself = i0 * (Wa[lane] + Wa[64 + lane]) + i1v * (Wa[lane + 32] + Wa[96 + lane]);
    float dcust = i0 * Wb[lane] + i1v * Wb[lane + 32] + f0 * Wb[64 + lane] + f1 * Wb[96 + lane];
    dself = warp_sum(dself); dcust = warp_sum(dcust);
    float aself = att_scalar(dself, a1b[k],     a2w[k],     a2b[k])     + 1.0f;
    float acust = att_scalar(dcust, a1b[k + 1], a2w[k + 1], a2b[k + 1]) + 1.0f;
    float s = aself + acust;
    float wsf = aself / s, wcu = acust / s;
    float* op = out + (size_t)node * DD;
    op[lane]      = wsf * i0  + wcu * f0;
    op[lane + 32] = wsf * i1v + wcu * f1;
}

__global__ void __launch_bounds__(256) k_final(const float* __restrict__ u0,
                                               const float* __restrict__ u1,
                                               const float* __restrict__ u2,
                                               const float* __restrict__ i0,
                                               const float* __restrict__ i1,
                                               const float* __restrict__ i2,
                                               const int* __restrict__ uidx,
                                               const int* __restrict__ iidx,
                                               float* __restrict__ out, int B) {
    int b = (blockIdx.x * blockDim.x + threadIdx.x) >> 5;
    int lane = threadIdx.x & 31;
    if (b >= B) return;
    size_t uo = (size_t)uidx[b] * DD, io = (size_t)iidx[b] * DD;
    float d = u0[uo + lane] * i0[io + lane] + u0[uo + lane + 32] * i0[io + lane + 32]
            + u1[uo + lane] * i1[io + lane] + u1[uo + lane + 32] * i1[io + lane + 32]
            + u2[uo + lane] * i2[io + lane] + u2[uo + lane + 32] * i2[io + lane + 32];
    d = warp_sum(d);
    if (lane == 0) out[b] = 1.f / (1.f + expf(-d));
}

// ---------------- launch ------------------------------------------------------
extern "C" void kernel_launch(void* const* d_in, const int* in_sizes, int n_in,
                              void* d_out, int out_size) {
    const float* u_emb = (const float*)d_in[0];
    const float* i_emb = (const float*)d_in[1];
    const float* snii1 = (const float*)d_in[2];
    const float* snii2 = (const float*)d_in[3];
    const float* ciii1 = (const float*)d_in[4];
    const float* ciii2 = (const float*)d_in[5];
    const float* icii1 = (const float*)d_in[6];
    const float* icii2 = (const float*)d_in[7];
    const float* law   = (const float*)d_in[8];
    const float* lab   = (const float*)d_in[9];
    const float* a1W   = (const float*)d_in[10];
    const float* a1b   = (const float*)d_in[11];
    const float* a2w   = (const float*)d_in[12];
    const float* a2b   = (const float*)d_in[13];
    const int* sn_row  = (const int*)d_in[14];
    const int* sn_col  = (const int*)d_in[15];
    const int* ci_row  = (const int*)d_in[16];
    const int* ci_col  = (const int*)d_in[17];
    const int* ic_row  = (const int*)d_in[18];
    const int* ic_col  = (const int*)d_in[19];
    const int* uidx    = (const int*)d_in[20];
    const int* iidx    = (const int*)d_in[21];
    float* out = (float*)d_out;
    int B = out_size;

    float2 *v12a, *v12b; int *colp, *cnt, *rowptr, *cursor, *bsum; float *np;
    cudaGetSymbolAddress((void**)&v12a, g_v12a);
    cudaGetSymbolAddress((void**)&v12b, g_v12b);
    cudaGetSymbolAddress((void**)&colp, g_colp);
    cudaGetSymbolAddress((void**)&cnt, g_cnt);
    cudaGetSymbolAddress((void**)&rowptr, g_rowptr);
    cudaGetSymbolAddress((void**)&cursor, g_cursor);
    cudaGetSymbolAddress((void**)&bsum, g_bsum);
    cudaGetSymbolAddress((void**)&np, g_node);

    float* ufi = np;
    float* ufu = ufi + (size_t)NU * DD;
    float* ifu = ufu + (size_t)NU * DD;
    float* u1  = ifu + (size_t)NI * DD;
    float* u2  = u1  + (size_t)NU * DD;
    float* i1  = u2  + (size_t)NU * DD;
    float* i2  = i1  + (size_t)NI * DD;

    const int T = 256;

    // ---- CSR build ----
    k_zero_int<<<CDIV(NROWS, T), T>>>(cnt, NROWS);
    k_hist<<<CDIV(ES, T), T>>>(sn_row, 0, ES, cnt);
    k_hist<<<CDIV(EUI, T), T>>>(ci_row, NU, EUI, cnt);
    k_hist<<<CDIV(EIU, T), T>>>(ic_row, 2 * NU, EIU, cnt);
    k_scan1<<<NSCANBLK, 1024>>>(cnt, rowptr, bsum, NROWS);
    k_scan2<<<1, 256>>>(bsum, NSCANBLK);
    k_scan3<<<CDIV(NROWS, T), T>>>(rowptr, cursor, bsum, NROWS);

    // ---- edge logits (original order, coalesced) ----
    k_logit<<<CDIV(ES, T), T>>>(snii1, snii2, law, lab, 0, 1, v12a, ES);
    k_logit<<<CDIV(EUI, T), T>>>(ciii1, ciii2, law, lab, 2, 3, v12a + ES, EUI);
    k_logit<<<CDIV(EIU, T), T>>>(icii1, icii2, law, lab, 4, 5, v12a + ES + EUI, EIU);

    // ---- scatter to row-sorted order ----
    k_scatter<<<CDIV(ES, T), T>>>(sn_row, sn_col, v12a, 0, ES, cursor, colp, v12b);
    k_scatter<<<CDIV(EUI, T), T>>>(ci_row, ci_col, v12a + ES, NU, EUI, cursor, colp, v12b);
    k_scatter<<<CDIV(EIU, T), T>>>(ic_row, ic_col, v12a + ES + EUI, 2 * NU, EIU, cursor, colp, v12b);

    // ---- row softmax (both components, atomic-free) ----
    k_softmax<<<CDIV(NROWS * 32, T), T>>>(rowptr, v12b);

    // ---- layer 1 ----
    k_spmm_row<0><<<CDIV(NU * 32, T), T>>>(v12b, colp, rowptr, (const float2*)u_emb, (float2*)ufu, 0, NU);
    k_spmm_row<0><<<CDIV(NU * 32, T), T>>>(v12b, colp, rowptr, (const float2*)i_emb, (float2*)ufi, NU, NU);
    k_spmm_row<0><<<CDIV(NI * 32, T), T>>>(v12b, colp, rowptr, (const float2*)u_emb, (float2*)ifu, 2 * NU, NI);
    k_user<<<CDIV(NU * 32, T), T>>>(u_emb, ufi, ufu, a1W, a1b, a2w, a2b, 0, u1);
    k_item<<<CDIV(NI * 32, T), T>>>(i_emb, ifu, a1W, a1b, a2w, a2b, 4, i1);

    // ---- layer 2 ----
    k_spmm_row<1><<<CDIV(NU * 32, T), T>>>(v12b, colp, rowptr, (const float2*)u1, (float2*)ufu, 0, NU);
    k_spmm_row<1><<<CDIV(NU * 32, T), T>>>(v12b, colp, rowptr, (const float2*)i1, (float2*)ufi, NU, NU);
    k_spmm_row<1><<<CDIV(NI * 32, T), T>>>(v12b, colp, rowptr, (const float2*)u1, (float2*)ifu, 2 * NU, NI);
    k_user<<<CDIV(NU * 32, T), T>>>(u1, ufi, ufu, a1W, a1b, a2w, a2b, 2, u2);
    k_item<<<CDIV(NI * 32, T), T>>>(i1, ifu, a1W, a1b, a2w, a2b, 6, i2);

    // ---- final ----
    k_final<<<CDIV(B * 32, T), T>>>(u_emb, u1, u2, i_emb, i1, i2, uidx, iidx, out, B);
}